// round 6
// baseline (speedup 1.0000x reference)
#include <cuda_runtime.h>
#include <cuda_bf16.h>

using u64 = unsigned long long;

__device__ __forceinline__ void fma2(u64& d, u64 a, u64 b) {
    asm("fma.rn.f32x2 %0, %1, %2, %0;" : "+l"(d) : "l"(a), "l"(b));
}
__device__ __forceinline__ u64 fma2n(u64 a, u64 b, u64 c) {
    u64 d;
    asm("fma.rn.f32x2 %0, %1, %2, %3;" : "=l"(d) : "l"(a), "l"(b), "l"(c));
    return d;
}
__device__ __forceinline__ u64 pack2(float x, float y) {
    u64 d;
    asm("mov.b64 %0, {%1, %2};" : "=l"(d) : "f"(x), "f"(y));
    return d;
}
__device__ __forceinline__ void unpack2(u64 v, float& x, float& y) {
    asm("mov.b64 {%0, %1}, %2;" : "=f"(x), "=f"(y) : "l"(v));
}
__device__ __forceinline__ void cp_async16(void* smem, const void* gmem) {
    unsigned s = (unsigned)__cvta_generic_to_shared(smem);
    asm volatile("cp.async.cg.shared.global [%0], [%1], 16;" :: "r"(s), "l"(gmem));
}
__device__ __forceinline__ void cp_commit() {
    asm volatile("cp.async.commit_group;");
}
template <int N>
__device__ __forceinline__ void cp_wait() {
    asm volatile("cp.async.wait_group %0;" :: "n"(N));
}

constexpr int TILE = 512;    // rows per CTA-tile (2 per thread)
constexpr int WARPS = 8;     // blockDim = 256

// Finish phase for one row given its two accumulator sets.
__device__ __forceinline__ void finish_row(const u64 acc1[5], const u64 acc2[5],
                                           float res[19]) {
    const u64 NEG1 = pack2(-1.0f, -1.0f);
    const u64 ONE1 = pack2(1.0f, 1.0f);
    float u[10], v[10];
#pragma unroll
    for (int q = 0; q < 5; ++q) {
        float x, y;
        unpack2(fma2n(acc1[q], NEG1, ONE1), x, y);
        u[2 * q]     = fminf(fmaxf(x, 1e-6f), 1.0f - 1e-6f);
        u[2 * q + 1] = fminf(fmaxf(y, 1e-6f), 1.0f - 1e-6f);
        unpack2(fma2n(acc2[q], NEG1, ONE1), x, y);
        v[2 * q]     = fminf(fmaxf(x, 1e-6f), 1.0f - 1e-6f);
        v[2 * q + 1] = fminf(fmaxf(y, 1e-6f), 1.0f - 1e-6f);
    }

    float prod[19];
#pragma unroll
    for (int j = 0; j < 10; ++j) prod[j] = fmaxf(u[0], v[j]);     // i = 0 row
#pragma unroll
    for (int i = 1; i < 10; ++i) prod[9 + i] = fmaxf(u[i], v[9]); // j = 9 col
#pragma unroll
    for (int i = 1; i < 10; ++i) {
#pragma unroll
        for (int j = 0; j < 9; ++j)
            prod[i + j] *= fmaxf(u[i], v[j]);
    }

    float sum = 0.0f;
#pragma unroll
    for (int k = 0; k < 19; ++k) {
        res[k] = 1.0f - prod[k];
        sum += res[k];
    }
    float inv = __fdividef(1.0f, sum + 1e-9f);
#pragma unroll
    for (int k = 0; k < 19; ++k) res[k] *= inv;
}

// Two rows per call: shares every P load/pack across both rows and doubles
// the independent FFMA2 streams available to the scheduler.
__device__ __forceinline__ void compute_rows2(const float2 av[2][5], const float2 bv[2][5],
                                              const float (*sPt)[10][12],
                                              float res[2][19]) {
    u64 acc1[2][5], acc2[2][5];
#pragma unroll
    for (int r = 0; r < 2; ++r)
#pragma unroll
        for (int q = 0; q < 5; ++q) { acc1[r][q] = 0ULL; acc2[r][q] = 0ULL; }

#pragma unroll
    for (int jj = 0; jj < 5; ++jj) {
#pragma unroll
        for (int h = 0; h < 2; ++h) {
            int j = jj * 2 + h;
            // P rows loaded ONCE, used for both rows
            const ulonglong2* r1 = (const ulonglong2*)&sPt[0][j][0];
            const ulonglong2* r2 = (const ulonglong2*)&sPt[1][j][0];
            ulonglong2 p01 = r1[0], p23 = r1[1];
            u64 p4 = ((const u64*)&sPt[0][j][0])[4];
            ulonglong2 q01 = r2[0], q23 = r2[1];
            u64 q4 = ((const u64*)&sPt[1][j][0])[4];
#pragma unroll
            for (int r = 0; r < 2; ++r) {
                float aj = h ? av[r][jj].y : av[r][jj].x;
                float bj = h ? bv[r][jj].y : bv[r][jj].x;
                u64 a2 = pack2(aj, aj);
                u64 b2 = pack2(bj, bj);
                fma2(acc1[r][0], a2, p01.x);
                fma2(acc1[r][1], a2, p01.y);
                fma2(acc1[r][2], a2, p23.x);
                fma2(acc1[r][3], a2, p23.y);
                fma2(acc1[r][4], a2, p4);
                fma2(acc2[r][0], b2, q01.x);
                fma2(acc2[r][1], b2, q01.y);
                fma2(acc2[r][2], b2, q23.x);
                fma2(acc2[r][3], b2, q23.y);
                fma2(acc2[r][4], b2, q4);
            }
        }
    }

#pragma unroll
    for (int r = 0; r < 2; ++r)
        finish_row(acc1[r], acc2[r], res[r]);
}

__global__ __launch_bounds__(256, 2)
void bacon_kernel(const float* __restrict__ p1,
                  const float* __restrict__ p2,
                  const float* __restrict__ W1,
                  const float* __restrict__ W2,
                  float* __restrict__ out,
                  int B) {
    // per-warp private slab: 64 rows -> p1 [0,640) + p2 [640,1280) floats;
    // reused for output staging (64*19 = 1216 floats). No block barriers after init.
    __shared__ __align__(16) float ws[WARPS][1280];
    __shared__ __align__(16) float sPt[2][10][12];   // transposed: sPt[m][j][i]

    const int tid  = threadIdx.x;
    const int lane = tid & 31;
    const int w    = tid >> 5;
    const int t    = blockIdx.x;

    // Inline soft-perm prep: threads 0..19.
    if (tid < 20) {
        const float* W = (tid < 10) ? W1 : W2;
        int r = tid % 10, m = tid / 10;
        float row[10];
        float lo = 1e30f, hi = -1e30f;
#pragma unroll
        for (int j = 0; j < 10; ++j) {
            row[j] = W[r * 10 + j];
            lo = fminf(lo, row[j]);
            hi = fmaxf(hi, row[j]);
        }
        float invr = 1.0f / (hi - lo + 1e-8f);
        float s = 0.0f;
#pragma unroll
        for (int j = 0; j < 10; ++j) {
            row[j] = (row[j] - lo) * invr;
            s += row[j];
        }
        float invs = 1.0f / (s + 1e-8f);
#pragma unroll
        for (int j = 0; j < 10; ++j)
            sPt[m][j][r] = row[j] * invs;
    }
    __syncthreads();   // the only block barrier

    const int slab0 = t * TILE + w * 64;    // this warp's 64 rows

    if (slab0 + 64 <= B) {
        // ---- fast path: stage 64 rows (160 float4 per input array) ----
        const float4* g1 = (const float4*)p1 + (size_t)t * 1280 + w * 160;
        const float4* g2 = (const float4*)p2 + (size_t)t * 1280 + w * 160;
        float4* s4 = (float4*)ws[w];
#pragma unroll
        for (int i = 0; i < 5; ++i) cp_async16(&s4[lane + i * 32], g1 + lane + i * 32);
#pragma unroll
        for (int i = 0; i < 5; ++i) cp_async16(&s4[160 + lane + i * 32], g2 + lane + i * 32);
        cp_commit();
        cp_wait<0>();
        __syncwarp();

        const float* sl = ws[w];
        float2 av[2][5], bv[2][5];
#pragma unroll
        for (int jj = 0; jj < 5; ++jj) {
            av[0][jj] = *(const float2*)&sl[lane * 10 + jj * 2];
            av[1][jj] = *(const float2*)&sl[(lane + 32) * 10 + jj * 2];
            bv[0][jj] = *(const float2*)&sl[640 + lane * 10 + jj * 2];
            bv[1][jj] = *(const float2*)&sl[640 + (lane + 32) * 10 + jj * 2];
        }
        __syncwarp();   // all input reads done before output staging overwrites

        float res[2][19];
        compute_rows2(av, bv, sPt, res);

        // stage output (stride 19: conflict-free), then coalesced float4 copy
        float* so = ws[w];
#pragma unroll
        for (int k = 0; k < 19; ++k) {
            so[lane * 19 + k]        = res[0][k];
            so[(lane + 32) * 19 + k] = res[1][k];
        }
        __syncwarp();

        float4* og = (float4*)out + (size_t)t * 2432 + w * 304;   // 64*19/4 = 304
        const float4* sv = (const float4*)so;
#pragma unroll
        for (int i = 0; i < 10; ++i) {
            int idx = lane + i * 32;
            if (idx < 304) og[idx] = sv[idx];
        }
    } else if (slab0 < B) {
        // ---- tail slab: scalar loads/stores, guarded per row ----
        int r0 = slab0 + lane;
        int r1 = slab0 + 32 + lane;
        float2 av[2][5], bv[2][5];
#pragma unroll
        for (int jj = 0; jj < 5; ++jj) {
            av[0][jj] = make_float2(0.f, 0.f); bv[0][jj] = make_float2(0.f, 0.f);
            av[1][jj] = make_float2(0.f, 0.f); bv[1][jj] = make_float2(0.f, 0.f);
        }
        if (r0 < B) {
#pragma unroll
            for (int jj = 0; jj < 5; ++jj) {
                av[0][jj] = *(const float2*)&p1[(size_t)r0 * 10 + jj * 2];
                bv[0][jj] = *(const float2*)&p2[(size_t)r0 * 10 + jj * 2];
            }
        }
        if (r1 < B) {
#pragma unroll
            for (int jj = 0; jj < 5; ++jj) {
                av[1][jj] = *(const float2*)&p1[(size_t)r1 * 10 + jj * 2];
                bv[1][jj] = *(const float2*)&p2[(size_t)r1 * 10 + jj * 2];
            }
        }
        float res[2][19];
        compute_rows2(av, bv, sPt, res);
        if (r0 < B) {
#pragma unroll
            for (int k = 0; k < 19; ++k) out[(size_t)r0 * 19 + k] = res[0][k];
        }
        if (r1 < B) {
#pragma unroll
            for (int k = 0; k < 19; ++k) out[(size_t)r1 * 19 + k] = res[1][k];
        }
    }
}

extern "C" void kernel_launch(void* const* d_in, const int* in_sizes, int n_in,
                              void* d_out, int out_size) {
    const float* p1 = (const float*)d_in[0];
    const float* p2 = (const float*)d_in[1];
    const float* W1 = (const float*)d_in[2];
    const float* W2 = (const float*)d_in[3];
    float* out = (float*)d_out;

    int B = in_sizes[0] / 10;
    int ntiles = (B + TILE - 1) / TILE;   // B=262144 -> 512 tiles, 1 per CTA

    bacon_kernel<<<ntiles, 256>>>(p1, p2, W1, W2, out, B);
}

// round 7
// speedup vs baseline: 1.1179x; 1.1179x over previous
#include <cuda_runtime.h>
#include <cuda_bf16.h>

using u64 = unsigned long long;

__device__ __forceinline__ void fma2(u64& d, u64 a, u64 b) {
    asm("fma.rn.f32x2 %0, %1, %2, %0;" : "+l"(d) : "l"(a), "l"(b));
}
__device__ __forceinline__ u64 fma2n(u64 a, u64 b, u64 c) {
    u64 d;
    asm("fma.rn.f32x2 %0, %1, %2, %3;" : "=l"(d) : "l"(a), "l"(b), "l"(c));
    return d;
}
__device__ __forceinline__ u64 pack2(float x, float y) {
    u64 d;
    asm("mov.b64 %0, {%1, %2};" : "=l"(d) : "f"(x), "f"(y));
    return d;
}
__device__ __forceinline__ void unpack2(u64 v, float& x, float& y) {
    asm("mov.b64 {%0, %1}, %2;" : "=f"(x), "=f"(y) : "l"(v));
}
__device__ __forceinline__ void cp_async16(void* smem, const void* gmem) {
    unsigned s = (unsigned)__cvta_generic_to_shared(smem);
    asm volatile("cp.async.cg.shared.global [%0], [%1], 16;" :: "r"(s), "l"(gmem));
}
__device__ __forceinline__ void cp_commit() {
    asm volatile("cp.async.commit_group;");
}
template <int N>
__device__ __forceinline__ void cp_wait() {
    asm volatile("cp.async.wait_group %0;" :: "n"(N));
}

constexpr int TILE = 256;   // rows per tile (== blockDim.x)
constexpr int WARPS = 8;

// Core per-row computation with FUSED matmuls:
// acc[i] = (l1_i, l2_i) accumulated with one packed FMA stream.
// sPtI[j][2i+m] = P_m[i][j]  (interleaved, 24-float rows, 16B aligned).
__device__ __forceinline__ void compute_row(const float2 av[5], const float2 bv[5],
                                            const float (*sPtI)[24],
                                            float res[19]) {
    u64 acc[10];
#pragma unroll
    for (int i = 0; i < 10; ++i) acc[i] = 0ULL;

#pragma unroll
    for (int jj = 0; jj < 5; ++jj) {
#pragma unroll
        for (int h = 0; h < 2; ++h) {
            int j = jj * 2 + h;
            float a = h ? av[jj].y : av[jj].x;
            float b = h ? bv[jj].y : bv[jj].x;
            u64 ab = pack2(a, b);                       // (p1_j, p2_j)
            const ulonglong2* r = (const ulonglong2*)&sPtI[j][0];
            ulonglong2 q0 = r[0], q1 = r[1], q2 = r[2], q3 = r[3], q4 = r[4];
            fma2(acc[0], ab, q0.x);
            fma2(acc[1], ab, q0.y);
            fma2(acc[2], ab, q1.x);
            fma2(acc[3], ab, q1.y);
            fma2(acc[4], ab, q2.x);
            fma2(acc[5], ab, q2.y);
            fma2(acc[6], ab, q3.x);
            fma2(acc[7], ab, q3.y);
            fma2(acc[8], ab, q4.x);
            fma2(acc[9], ab, q4.y);
        }
    }

    // (u_i, v_i) = 1 - (l1_i, l2_i); clamps dropped (error <= ~1e-6 rel, see notes)
    const u64 NEG1 = pack2(-1.0f, -1.0f);
    const u64 ONE1 = pack2(1.0f, 1.0f);
    float u[10], v[10];
#pragma unroll
    for (int i = 0; i < 10; ++i)
        unpack2(fma2n(acc[i], NEG1, ONE1), u[i], v[i]);

    // y_k = 1 - prod_{i+j=k} max(u_i, v_j)
    float prod[19];
#pragma unroll
    for (int j = 0; j < 10; ++j) prod[j] = fmaxf(u[0], v[j]);     // i = 0 row
#pragma unroll
    for (int i = 1; i < 10; ++i) prod[9 + i] = fmaxf(u[i], v[9]); // j = 9 col
#pragma unroll
    for (int i = 1; i < 10; ++i) {
#pragma unroll
        for (int j = 0; j < 9; ++j)
            prod[i + j] *= fmaxf(u[i], v[j]);
    }

    float sum = 0.0f;
#pragma unroll
    for (int k = 0; k < 19; ++k) {
        res[k] = 1.0f - prod[k];
        sum += res[k];
    }
    float inv = __fdividef(1.0f, sum + 1e-9f);
#pragma unroll
    for (int k = 0; k < 19; ++k) res[k] *= inv;
}

__global__ __launch_bounds__(TILE, 4)
void bacon_kernel(const float* __restrict__ p1,
                  const float* __restrict__ p2,
                  const float* __restrict__ W1,
                  const float* __restrict__ W2,
                  float* __restrict__ out,
                  int B, int ntiles) {
    // per-warp private double-buffered staging slices (2 x 640 floats):
    // buffer = p1 rows [0,320) + p2 rows [320,640); reused for output staging.
    __shared__ __align__(16) float ws[WARPS][2][640];
    __shared__ __align__(16) float sPtI[10][24];   // interleaved: [j][2i+m]

    const int tid  = threadIdx.x;
    const int lane = tid & 31;
    const int w    = tid >> 5;
    const int G    = gridDim.x;

    // Inline soft-perm prep: threads 0..19 (thread = matrix m, row r).
    if (tid < 20) {
        const float* W = (tid < 10) ? W1 : W2;
        int r = tid % 10, m = tid / 10;
        float row[10];
        float lo = 1e30f, hi = -1e30f;
#pragma unroll
        for (int j = 0; j < 10; ++j) {
            row[j] = W[r * 10 + j];
            lo = fminf(lo, row[j]);
            hi = fmaxf(hi, row[j]);
        }
        float invr = 1.0f / (hi - lo + 1e-8f);
        float s = 0.0f;
#pragma unroll
        for (int j = 0; j < 10; ++j) {
            row[j] = (row[j] - lo) * invr;
            s += row[j];
        }
        float invs = 1.0f / (s + 1e-8f);
#pragma unroll
        for (int j = 0; j < 10; ++j)
            sPtI[j][2 * r + m] = row[j] * invs;    // interleaved store
    }
    __syncthreads();   // the only block barrier

    // stage this warp's 32-row slab of tile t into buffer buf (fast path only)
    auto stage = [&](int buf, int t) {
        const float4* g1 = (const float4*)p1 + (size_t)t * 640 + w * 80;
        const float4* g2 = (const float4*)p2 + (size_t)t * 640 + w * 80;
        float4* s = (float4*)ws[w][buf];
#pragma unroll
        for (int i = 0; i < 5; ++i) {
            int idx = lane + i * 32;
            const float4* src = (idx < 80) ? (g1 + idx) : (g2 + (idx - 80));
            cp_async16(&s[idx], src);
        }
    };

    int cur = blockIdx.x;
    if (cur >= ntiles) return;
    const bool cur_full0 = (cur * TILE + (w + 1) * 32 <= B);
    if (cur_full0) { stage(0, cur); cp_commit(); }

    int p = 0;
    for (; cur < ntiles; cur += G) {
        const int nxt = cur + G;
        const bool cur_full = (cur * TILE + (w + 1) * 32 <= B);
        const bool nxt_full = (nxt < ntiles) && (nxt * TILE + (w + 1) * 32 <= B);

        if (nxt_full) { stage(1 - p, nxt); cp_commit(); }

        if (cur_full) {
            if (nxt_full) cp_wait<1>(); else cp_wait<0>();
            __syncwarp();

            float* slice = ws[w][p];
            float2 av[5], bv[5];
#pragma unroll
            for (int jj = 0; jj < 5; ++jj) {
                av[jj] = *(const float2*)&slice[lane * 10 + jj * 2];
                bv[jj] = *(const float2*)&slice[320 + lane * 10 + jj * 2];
            }
            __syncwarp();   // input reads done before output staging overwrites

            float res[19];
            compute_row(av, bv, sPtI, res);

#pragma unroll
            for (int k = 0; k < 19; ++k) slice[lane * 19 + k] = res[k];  // stride 19: conflict-free
            __syncwarp();

            float4* og = (float4*)out + (size_t)cur * 1216 + w * 152;
            const float4* sv = (const float4*)slice;
#pragma unroll
            for (int i = 0; i < 5; ++i) {
                int idx = lane + i * 32;
                if (idx < 152) og[idx] = sv[idx];
            }
            __syncwarp();   // copy reads done before this buffer's next prefetch
        } else {
            // tail slab: scalar, no smem
            cp_wait<0>();
            int row = cur * TILE + w * 32 + lane;
            if (row < B) {
                float2 av[5], bv[5];
#pragma unroll
                for (int jj = 0; jj < 5; ++jj) {
                    av[jj] = *(const float2*)&p1[(size_t)row * 10 + jj * 2];
                    bv[jj] = *(const float2*)&p2[(size_t)row * 10 + jj * 2];
                }
                float res[19];
                compute_row(av, bv, sPtI, res);
#pragma unroll
                for (int k = 0; k < 19; ++k)
                    out[(size_t)row * 19 + k] = res[k];
            }
            __syncwarp();
        }
        p ^= 1;
    }
}

extern "C" void kernel_launch(void* const* d_in, const int* in_sizes, int n_in,
                              void* d_out, int out_size) {
    const float* p1 = (const float*)d_in[0];
    const float* p2 = (const float*)d_in[1];
    const float* W1 = (const float*)d_in[2];
    const float* W2 = (const float*)d_in[3];
    float* out = (float*)d_out;

    int B = in_sizes[0] / 10;
    int ntiles = (B + TILE - 1) / TILE;

    // one balanced wave at occupancy 4 on 148 SMs (verified ~1% makespan tail)
    int G = 592;
    if (G > ntiles) G = ntiles;
    if (G < 1) G = 1;

    bacon_kernel<<<G, TILE>>>(p1, p2, W1, W2, out, B, ntiles);
}

// round 9
// speedup vs baseline: 1.1375x; 1.0175x over previous
#include <cuda_runtime.h>
#include <cuda_bf16.h>

using u64 = unsigned long long;

__device__ __forceinline__ void fma2(u64& d, u64 a, u64 b) {
    asm("fma.rn.f32x2 %0, %1, %2, %0;" : "+l"(d) : "l"(a), "l"(b));
}
__device__ __forceinline__ u64 pack2(float x, float y) {
    u64 d;
    asm("mov.b64 %0, {%1, %2};" : "=l"(d) : "f"(x), "f"(y));
    return d;
}
__device__ __forceinline__ void unpack2(u64 v, float& x, float& y) {
    asm("mov.b64 {%0, %1}, %2;" : "=f"(x), "=f"(y) : "l"(v));
}
__device__ __forceinline__ void cp_async16(void* smem, const void* gmem) {
    unsigned s = (unsigned)__cvta_generic_to_shared(smem);
    asm volatile("cp.async.cg.shared.global [%0], [%1], 16;" :: "r"(s), "l"(gmem));
}
__device__ __forceinline__ void cp_commit() {
    asm volatile("cp.async.commit_group;");
}
template <int N>
__device__ __forceinline__ void cp_wait() {
    asm volatile("cp.async.wait_group %0;" :: "n"(N));
}

constexpr int TILE = 256;   // rows per tile (== blockDim.x)
constexpr int WARPS = 8;

// Core per-row computation.
// sPtI[j][2i+m] = -P_m[i][j]  (NEGATED + interleaved, 24-float rows).
// acc[i] starts at (1,1), so after the fused matmul:
//   acc[i] = (1 - l1_i, 1 - l2_i) = (u_i, v_i)   -- epilogue-free.
// Then y_k = 1 - prod_{i+j=k} max(u_i, v_j), normalized.
__device__ __forceinline__ void compute_row(const float2 av[5], const float2 bv[5],
                                            const float (*sPtI)[24],
                                            float res[19]) {
    u64 acc[10];
    const u64 ONE2 = pack2(1.0f, 1.0f);
#pragma unroll
    for (int i = 0; i < 10; ++i) acc[i] = ONE2;

#pragma unroll
    for (int jj = 0; jj < 5; ++jj) {
#pragma unroll
        for (int h = 0; h < 2; ++h) {
            int j = jj * 2 + h;
            float a = h ? av[jj].y : av[jj].x;
            float b = h ? bv[jj].y : bv[jj].x;
            u64 ab = pack2(a, b);                       // (p1_j, p2_j)
            const ulonglong2* r = (const ulonglong2*)&sPtI[j][0];
            ulonglong2 q0 = r[0], q1 = r[1], q2 = r[2], q3 = r[3], q4 = r[4];
            fma2(acc[0], ab, q0.x);
            fma2(acc[1], ab, q0.y);
            fma2(acc[2], ab, q1.x);
            fma2(acc[3], ab, q1.y);
            fma2(acc[4], ab, q2.x);
            fma2(acc[5], ab, q2.y);
            fma2(acc[6], ab, q3.x);
            fma2(acc[7], ab, q3.y);
            fma2(acc[8], ab, q4.x);
            fma2(acc[9], ab, q4.y);
        }
    }

    float u[10], v[10];
#pragma unroll
    for (int i = 0; i < 10; ++i) unpack2(acc[i], u[i], v[i]);

    // y_k = 1 - prod_{i+j=k} max(u_i, v_j)
    float prod[19];
#pragma unroll
    for (int j = 0; j < 10; ++j) prod[j] = fmaxf(u[0], v[j]);     // i = 0 row
#pragma unroll
    for (int i = 1; i < 10; ++i) prod[9 + i] = fmaxf(u[i], v[9]); // j = 9 col
#pragma unroll
    for (int i = 1; i < 10; ++i) {
#pragma unroll
        for (int j = 0; j < 9; ++j)
            prod[i + j] *= fmaxf(u[i], v[j]);
    }

    // res = 1 - prod; normalize. Pairwise sum tree (shorter dep chain).
    float s0 = 0.f, s1 = 0.f, s2 = 0.f, s3 = 0.f;
#pragma unroll
    for (int k = 0; k < 19; ++k) {
        res[k] = 1.0f - prod[k];
        if ((k & 3) == 0) s0 += res[k];
        else if ((k & 3) == 1) s1 += res[k];
        else if ((k & 3) == 2) s2 += res[k];
        else s3 += res[k];
    }
    float sum = (s0 + s1) + (s2 + s3);
    float inv = __fdividef(1.0f, sum + 1e-9f);
#pragma unroll
    for (int k = 0; k < 19; ++k) res[k] *= inv;
}

__global__ __launch_bounds__(TILE, 4)
void bacon_kernel(const float* __restrict__ p1,
                  const float* __restrict__ p2,
                  const float* __restrict__ W1,
                  const float* __restrict__ W2,
                  float* __restrict__ out,
                  int B, int ntiles) {
    // per-warp private double-buffered staging slices (2 x 640 floats):
    // buffer = p1 rows [0,320) + p2 rows [320,640); reused for output staging.
    __shared__ __align__(16) float ws[WARPS][2][640];
    __shared__ __align__(16) float sPtI[10][24];   // interleaved NEGATED: [j][2i+m]

    const int tid  = threadIdx.x;
    const int lane = tid & 31;
    const int w    = tid >> 5;
    const int G    = gridDim.x;

    // Inline soft-perm prep: threads 0..19 (thread = matrix m, row r).
    if (tid < 20) {
        const float* W = (tid < 10) ? W1 : W2;
        int r = tid % 10, m = tid / 10;
        float row[10];
        float lo = 1e30f, hi = -1e30f;
#pragma unroll
        for (int j = 0; j < 10; ++j) {
            row[j] = W[r * 10 + j];
            lo = fminf(lo, row[j]);
            hi = fmaxf(hi, row[j]);
        }
        float invr = 1.0f / (hi - lo + 1e-8f);
        float s = 0.0f;
#pragma unroll
        for (int j = 0; j < 10; ++j) {
            row[j] = (row[j] - lo) * invr;
            s += row[j];
        }
        float invs = 1.0f / (s + 1e-8f);
#pragma unroll
        for (int j = 0; j < 10; ++j)
            sPtI[j][2 * r + m] = -(row[j] * invs);   // NEGATED interleaved store
    }
    __syncthreads();   // the only block barrier

    // stage this warp's 32-row slab of tile t into buffer buf (fast path only)
    auto stage = [&](int buf, int t) {
        const float4* g1 = (const float4*)p1 + (size_t)t * 640 + w * 80;
        const float4* g2 = (const float4*)p2 + (size_t)t * 640 + w * 80;
        float4* s = (float4*)ws[w][buf];
#pragma unroll
        for (int i = 0; i < 5; ++i) {
            int idx = lane + i * 32;
            const float4* src = (idx < 80) ? (g1 + idx) : (g2 + (idx - 80));
            cp_async16(&s[idx], src);
        }
    };

    int cur = blockIdx.x;
    if (cur >= ntiles) return;
    const bool cur_full0 = (cur * TILE + (w + 1) * 32 <= B);
    if (cur_full0) { stage(0, cur); cp_commit(); }

    int p = 0;
    for (; cur < ntiles; cur += G) {
        const int nxt = cur + G;
        const bool cur_full = (cur * TILE + (w + 1) * 32 <= B);
        const bool nxt_full = (nxt < ntiles) && (nxt * TILE + (w + 1) * 32 <= B);

        if (nxt_full) { stage(1 - p, nxt); cp_commit(); }

        if (cur_full) {
            if (nxt_full) cp_wait<1>(); else cp_wait<0>();
            __syncwarp();

            float* slice = ws[w][p];
            float2 av[5], bv[5];
#pragma unroll
            for (int jj = 0; jj < 5; ++jj) {
                av[jj] = *(const float2*)&slice[lane * 10 + jj * 2];
                bv[jj] = *(const float2*)&slice[320 + lane * 10 + jj * 2];
            }
            __syncwarp();   // input reads done before output staging overwrites

            float res[19];
            compute_row(av, bv, sPtI, res);

#pragma unroll
            for (int k = 0; k < 19; ++k) slice[lane * 19 + k] = res[k];  // stride 19: conflict-free
            __syncwarp();

            float4* og = (float4*)out + (size_t)cur * 1216 + w * 152;
            const float4* sv = (const float4*)slice;
#pragma unroll
            for (int i = 0; i < 5; ++i) {
                int idx = lane + i * 32;
                if (idx < 152) og[idx] = sv[idx];
            }
            __syncwarp();   // copy reads done before this buffer's next prefetch
        } else {
            // tail slab: scalar, no smem
            cp_wait<0>();
            int row = cur * TILE + w * 32 + lane;
            if (row < B) {
                float2 av[5], bv[5];
#pragma unroll
                for (int jj = 0; jj < 5; ++jj) {
                    av[jj] = *(const float2*)&p1[(size_t)row * 10 + jj * 2];
                    bv[jj] = *(const float2*)&p2[(size_t)row * 10 + jj * 2];
                }
                float res[19];
                compute_row(av, bv, sPtI, res);
#pragma unroll
                for (int k = 0; k < 19; ++k)
                    out[(size_t)row * 19 + k] = res[k];
            }
            __syncwarp();
        }
        p ^= 1;
    }
}

extern "C" void kernel_launch(void* const* d_in, const int* in_sizes, int n_in,
                              void* d_out, int out_size) {
    const float* p1 = (const float*)d_in[0];
    const float* p2 = (const float*)d_in[1];
    const float* W1 = (const float*)d_in[2];
    const float* W2 = (const float*)d_in[3];
    float* out = (float*)d_out;

    int B = in_sizes[0] / 10;
    int ntiles = (B + TILE - 1) / TILE;

    // one balanced wave at occupancy 4 on 148 SMs (~1% makespan tail)
    int G = 592;
    if (G > ntiles) G = ntiles;
    if (G < 1) G = 1;

    bacon_kernel<<<G, TILE>>>(p1, p2, W1, W2, out, B, ntiles);
}